// round 7
// baseline (speedup 1.0000x reference)
#include <cuda_runtime.h>
#include <cuda_bf16.h>
#include <stdint.h>

// Shapes (fixed):
//   updates: (8,128,128,256) float32 -> 33,554,432 elems
//   mask:    same shape int32 in [0, 16,777,216)
//   output:  (8,256,256,256) float32 -> 134,217,728 elems (512 MB)
// out[mask[i] + (i>>22)<<22] += updates[i]; rest zeros.
// Scatter region = [0, 46,137,344) (184 MB); tail (352 MB) never touched.
//
// Critical path: memset W0 -> pass0(atomics W0) -> memset W1 -> pass1(atomics W1)
// Tail zero-fill: SMALL persistent grid on a forked stream, co-resident with
// the passes (atomic-slot-bound passes leave >50% LTS + LSU headroom).

#define N_ELEMS      33554432u
#define N_VEC4       (N_ELEMS / 4u)             // 8,388,608
#define BATCH_V4_SH  20
#define BATCH_OFF_SH 22
#define SCATTER_END  46137344u
#define W_SPLIT      23068672u                  // W0=[0,W_SPLIT) W1=[W_SPLIT,END)
#define OUT_ELEMS    134217728u
#define TAIL_START_V4 (SCATTER_END / 4u)        // 11,534,336
#define TAIL_V4      ((OUT_ELEMS - SCATTER_END) / 4u)  // 22,020,096

#define TAIL_BLOCKS  296                        // ~2 CTAs per SM, co-resident

__global__ __launch_bounds__(256, 8)
void scatter_pass_kernel(const float4* __restrict__ upd4,
                         const int4*  __restrict__ msk4,
                         float* __restrict__ out,
                         unsigned int wlo, unsigned int whi)
{
    unsigned int i = blockIdx.x * 256u + threadIdx.x;   // [0, N_VEC4)

    float4 u = __ldcs(upd4 + i);
    int4   m = __ldcs(msk4 + i);

    unsigned int base = (i >> BATCH_V4_SH) << BATCH_OFF_SH;
    unsigned int ix = base + (unsigned int)m.x;
    unsigned int iy = base + (unsigned int)m.y;
    unsigned int iz = base + (unsigned int)m.z;
    unsigned int iw = base + (unsigned int)m.w;

    // Atomics only into the current L2-resident window.
    if (ix >= wlo && ix < whi) atomicAdd(out + ix, u.x);
    if (iy >= wlo && iy < whi) atomicAdd(out + iy, u.y);
    if (iz >= wlo && iz < whi) atomicAdd(out + iz, u.z);
    if (iw >= wlo && iw < whi) atomicAdd(out + iw, u.w);
}

// Persistent grid-stride tail zero-fill: tiny grid so it coexists with the
// scatter passes instead of monopolizing the SMs. Write-through stores (no L2
// allocation) so it never evicts the atomic window.
__global__ __launch_bounds__(256, 2)
void zero_tail_kernel(float4* __restrict__ out4)
{
    const float4 z = make_float4(0.f, 0.f, 0.f, 0.f);
    unsigned int stride = TAIL_BLOCKS * 256u;
    for (unsigned int t = blockIdx.x * 256u + threadIdx.x;
         t < TAIL_V4; t += stride)
        __stwt(out4 + TAIL_START_V4 + t, z);
}

extern "C" void kernel_launch(void* const* d_in, const int* in_sizes, int n_in,
                              void* d_out, int out_size)
{
    const float4* upd4 = (const float4*)d_in[0];
    const int4*   msk4 = (const int4*)d_in[1];
    float* out = (float*)d_out;

    static cudaStream_t side = nullptr;
    static cudaEvent_t ev_fork = nullptr, ev_join = nullptr;
    if (side == nullptr) {
        cudaStreamCreateWithFlags(&side, cudaStreamNonBlocking);
        cudaEventCreateWithFlags(&ev_fork, cudaEventDisableTiming);
        cudaEventCreateWithFlags(&ev_join, cudaEventDisableTiming);
    }

    const int threads = 256;
    const int blocks  = (int)(N_VEC4 / threads);   // 32768

    // Fork: co-resident persistent tail fill (352 MB) alongside the chain.
    cudaEventRecord(ev_fork, 0);
    cudaStreamWaitEvent(side, ev_fork, 0);
    zero_tail_kernel<<<TAIL_BLOCKS, threads, 0, side>>>((float4*)d_out);
    cudaEventRecord(ev_join, side);

    // Serial scatter chain (atomic-slot bound).
    cudaMemsetAsync(out, 0, (size_t)W_SPLIT * sizeof(float), 0);
    scatter_pass_kernel<<<blocks, threads>>>(upd4, msk4, out, 0u, W_SPLIT);
    cudaMemsetAsync(out + W_SPLIT, 0,
                    (size_t)(SCATTER_END - W_SPLIT) * sizeof(float), 0);
    scatter_pass_kernel<<<blocks, threads>>>(upd4, msk4, out,
                                             W_SPLIT, SCATTER_END);

    // Join: output complete only after both branches finish.
    cudaStreamWaitEvent(0, ev_join, 0);
}